// round 1
// baseline (speedup 1.0000x reference)
#include <cuda_runtime.h>
#include <math.h>
#include <stdint.h>

#define NN 50000
#define EE 800000
#define DD 64

// ---------------- device scratch (static, no allocation) ----------------
__device__ int   g_flag;                 // 1 if edge_index is int64
__device__ int   g_src[EE];
__device__ int   g_dst[EE];
__device__ int   g_cnt[NN];
__device__ int   g_rowptr[NN + 1];
__device__ int   g_fill[NN];
__device__ int   g_srcs[EE];             // src ids sorted by dst (CSR)
__device__ __align__(16) float g_buf[NN * DD];   // layer activation ping buffer
__device__ __align__(16) float g_h[NN * DD];     // per-conv h = x @ W
__device__ float g_ssrc[NN];
__device__ float g_sdst[NN];

// ---------------- dtype detection ----------------
// If edge_index is int64 (values < 2^31), every odd 32-bit word is 0.
__global__ void k_detect(const int* __restrict__ raw) {
    __shared__ int ok;
    if (threadIdx.x == 0) ok = 1;
    __syncthreads();
    // check 4096 odd words (indices 1,3,...,8191), all within 2*EE words
    for (int i = threadIdx.x; i < 4096; i += blockDim.x) {
        if (raw[2 * i + 1] != 0) ok = 0;
    }
    __syncthreads();
    if (threadIdx.x == 0) g_flag = ok;
}

__global__ void k_convert(const void* __restrict__ raw, int E) {
    int j = blockIdx.x * blockDim.x + threadIdx.x;
    if (j >= E) return;
    if (g_flag) {
        const long long* p = (const long long*)raw;
        g_src[j] = (int)p[j];
        g_dst[j] = (int)p[E + j];
    } else {
        const int* p = (const int*)raw;
        g_src[j] = p[j];
        g_dst[j] = p[E + j];
    }
}

// ---------------- CSR build ----------------
__global__ void k_zero_cnt() {
    int i = blockIdx.x * blockDim.x + threadIdx.x;
    if (i < NN) g_cnt[i] = 0;
}

__global__ void k_hist(int E) {
    int j = blockIdx.x * blockDim.x + threadIdx.x;
    if (j < E) atomicAdd(&g_cnt[g_dst[j]], 1);
}

__global__ void k_scan() {
    const int T = 1024;
    const int CH = (NN + T - 1) / T;   // 49
    __shared__ int sh[T];
    int tid = threadIdx.x;
    int begin = tid * CH;
    int end = begin + CH; if (end > NN) end = NN;
    if (begin > NN) begin = NN;
    int s = 0;
    for (int i = begin; i < end; i++) s += g_cnt[i];
    sh[tid] = s;
    __syncthreads();
    // inclusive Hillis-Steele scan
    for (int off = 1; off < T; off <<= 1) {
        int v = (tid >= off) ? sh[tid - off] : 0;
        __syncthreads();
        sh[tid] += v;
        __syncthreads();
    }
    int run = sh[tid] - s;   // exclusive prefix of this chunk
    for (int i = begin; i < end; i++) {
        g_rowptr[i] = run;
        g_fill[i] = run;
        run += g_cnt[i];
    }
    if (tid == T - 1) g_rowptr[NN] = sh[T - 1];
}

__global__ void k_scatter(int E) {
    int j = blockIdx.x * blockDim.x + threadIdx.x;
    if (j >= E) return;
    int d = g_dst[j];
    int pos = atomicAdd(&g_fill[d], 1);
    g_srcs[pos] = g_src[j];
}

// ---------------- GEMM + attention score projections ----------------
// h = x @ W  (row-major W[k*64+c]); also s_src = h@a_s, s_dst = h@a_d fused.
// Block: 256 threads = 8 warps; each warp does 8 rows; lane owns cols {2L,2L+1}.
__global__ void k_gemm(const float* __restrict__ xext, int use_ext,
                       const float* __restrict__ W,
                       const float* __restrict__ a_s,
                       const float* __restrict__ a_d) {
    __shared__ float Ws[DD * DD];
    const float* x = use_ext ? xext : g_buf;
    int tid = threadIdx.x;
    for (int i = tid; i < DD * DD; i += 256) Ws[i] = W[i];
    int lane = tid & 31, warp = tid >> 5;
    float2 as2 = ((const float2*)a_s)[lane];
    float2 ad2 = ((const float2*)a_d)[lane];
    __syncthreads();
    int rowbase = blockIdx.x * 64 + warp * 8;
    for (int r = 0; r < 8; r++) {
        int row = rowbase + r;
        if (row >= NN) return;
        float x0 = x[row * DD + lane];
        float x1 = x[row * DD + 32 + lane];
        float2 acc = make_float2(0.f, 0.f);
#pragma unroll
        for (int k = 0; k < DD; k++) {
            float xv = __shfl_sync(0xffffffffu, (k < 32) ? x0 : x1, k & 31);
            float2 w2 = *reinterpret_cast<const float2*>(&Ws[k * DD + 2 * lane]);
            acc.x = fmaf(xv, w2.x, acc.x);
            acc.y = fmaf(xv, w2.y, acc.y);
        }
        reinterpret_cast<float2*>(g_h)[row * 32 + lane] = acc;
        float ss = acc.x * as2.x + acc.y * as2.y;
        float sd = acc.x * ad2.x + acc.y * ad2.y;
#pragma unroll
        for (int o = 16; o; o >>= 1) {
            ss += __shfl_xor_sync(0xffffffffu, ss, o);
            sd += __shfl_xor_sync(0xffffffffu, sd, o);
        }
        if (lane == 0) { g_ssrc[row] = ss; g_sdst[row] = sd; }
    }
}

// ---------------- per-dst softmax + weighted aggregation ----------------
// One warp per destination node. No atomics; one coalesced float2 write per node.
__global__ void k_agg(float* __restrict__ yext, int use_ext) {
    int w = (blockIdx.x * blockDim.x + threadIdx.x) >> 5;
    int lane = threadIdx.x & 31;
    if (w >= NN) return;
    float* y = use_ext ? yext : g_buf;
    int start = g_rowptr[w], end = g_rowptr[w + 1];
    float sd = g_sdst[w];

    // pass 1: segment max
    float mx = -1e30f;
    for (int j = start + lane; j < end; j += 32) {
        float e = g_ssrc[g_srcs[j]] + sd;
        e = (e > 0.f) ? e : 0.2f * e;
        mx = fmaxf(mx, e);
    }
#pragma unroll
    for (int o = 16; o; o >>= 1) mx = fmaxf(mx, __shfl_xor_sync(0xffffffffu, mx, o));

    // pass 2: segment sum of exp
    float z = 0.f;
    for (int j = start + lane; j < end; j += 32) {
        float e = g_ssrc[g_srcs[j]] + sd;
        e = (e > 0.f) ? e : 0.2f * e;
        z += __expf(e - mx);
    }
#pragma unroll
    for (int o = 16; o; o >>= 1) z += __shfl_xor_sync(0xffffffffu, z, o);
    float inv = 1.f / (z + 1e-16f);

    // pass 3: weighted gather-accumulate; warp serializes edges, lanes span D
    float2 acc = make_float2(0.f, 0.f);
    const float2* h2 = reinterpret_cast<const float2*>(g_h);
    for (int j = start; j < end; j++) {
        int s = g_srcs[j];                      // uniform (broadcast) load
        float e = g_ssrc[s] + sd;               // uniform load + cheap math
        e = (e > 0.f) ? e : 0.2f * e;
        float wgt = __expf(e - mx) * inv;
        float2 hv = h2[s * 32 + lane];          // coalesced 256B per edge
        acc.x = fmaf(hv.x, wgt, acc.x);
        acc.y = fmaf(hv.y, wgt, acc.y);
    }
    reinterpret_cast<float2*>(y)[w * 32 + lane] = acc;
}

// ---------------- ELU ----------------
__global__ void k_elu(float* __restrict__ bext, int use_ext, int n) {
    float* b = use_ext ? bext : g_buf;
    int i = blockIdx.x * blockDim.x + threadIdx.x;
    if (i >= n) return;
    float v = b[i];
    b[i] = (v > 0.f) ? v : (__expf(v) - 1.f);
}

// ---------------- launch ----------------
extern "C" void kernel_launch(void* const* d_in, const int* in_sizes, int n_in,
                              void* d_out, int out_size) {
    const float* feat  = (const float*)d_in[0];
    const void*  eidx  = d_in[1];
    const float* W1    = (const float*)d_in[2];
    const float* a_s1  = (const float*)d_in[3];
    const float* a_d1  = (const float*)d_in[4];
    const float* W2    = (const float*)d_in[5];
    const float* a_s2  = (const float*)d_in[6];
    const float* a_d2  = (const float*)d_in[7];
    float* out = (float*)d_out;

    int E = in_sizes[1] / 2;   // 800000 for either int32 or int64 storage

    // CSR build (dst structure shared by all 8 convs)
    k_detect<<<1, 1024>>>((const int*)eidx);
    k_convert<<<(E + 255) / 256, 256>>>(eidx, E);
    k_zero_cnt<<<(NN + 255) / 256, 256>>>();
    k_hist<<<(E + 255) / 256, 256>>>(E);
    k_scan<<<1, 1024>>>();
    k_scatter<<<(E + 255) / 256, 256>>>(E);

    const int gemm_grid = (NN + 63) / 64;
    const int agg_grid  = (NN * 32 + 255) / 256;

    for (int layer = 0; layer < 2; layer++) {
        const float* W  = layer ? W2   : W1;
        const float* as = layer ? a_s2 : a_s1;
        const float* ad = layer ? a_d2 : a_d1;
        for (int head = 0; head < 4; head++) {
            int first = (layer == 0 && head == 0);
            int last  = (layer == 1 && head == 3);
            k_gemm<<<gemm_grid, 256>>>(feat, first, W + head * DD * DD,
                                       as + head * DD, ad + head * DD);
            k_agg<<<agg_grid, 256>>>(out, last);
        }
        // ELU at end of layer: layer 0 -> g_buf in place; layer 1 -> d_out
        k_elu<<<(NN * DD + 255) / 256, 256>>>(out, layer == 1, NN * DD);
    }
}

// round 2
// speedup vs baseline: 1.6747x; 1.6747x over previous
#include <cuda_runtime.h>
#include <math.h>
#include <stdint.h>

#define NN 50000
#define EE 800000
#define DD 64
#define BR 128   // rows per GEMM block

// ---------------- device scratch (static, no allocation) ----------------
__device__ int   g_flag;                 // 1 if edge_index is int64
__device__ int   g_cnt[NN];
__device__ int   g_rowptr[NN + 1];
__device__ int   g_fill[NN];
__device__ int   g_srcs[EE];             // src ids sorted by dst (CSR)
__device__ int   g_src[EE];
__device__ int   g_dst[EE];
__device__ __align__(16) float g_buf[NN * DD];   // layer activation buffer
__device__ __align__(16) float g_h[NN * DD];     // per-conv h = x @ W
__device__ float g_ssrc[NN];
__device__ float g_sdst[NN];

// ---------------- detect dtype + zero counters (launch 0) ----------------
// If edge_index is int64 (values < 2^31, little-endian), every odd 32-bit
// word of the first 2048 elements is 0.
__global__ void k_detect_zero(const int* __restrict__ raw) {
    int i = blockIdx.x * blockDim.x + threadIdx.x;
    if (i < NN) g_cnt[i] = 0;
    if (blockIdx.x == 0) {
        __shared__ int ok;
        if (threadIdx.x == 0) ok = 1;
        __syncthreads();
        for (int j = threadIdx.x; j < 4096; j += blockDim.x)
            if (raw[2 * j + 1] != 0) ok = 0;
        __syncthreads();
        if (threadIdx.x == 0) g_flag = ok;
    }
}

// ---------------- convert + histogram (launch 1) ----------------
__global__ void k_convert_hist(const void* __restrict__ raw, int E) {
    int j = blockIdx.x * blockDim.x + threadIdx.x;
    if (j >= E) return;
    int s, d;
    if (g_flag) {
        const long long* p = (const long long*)raw;
        s = (int)p[j]; d = (int)p[E + j];
    } else {
        const int* p = (const int*)raw;
        s = p[j]; d = p[E + j];
    }
    g_src[j] = s;
    g_dst[j] = d;
    atomicAdd(&g_cnt[d], 1);
}

// ---------------- single-block scan (launch 2) ----------------
__global__ void k_scan() {
    const int T = 1024;
    const int CH = (NN + T - 1) / T;
    __shared__ int sh[T];
    int tid = threadIdx.x;
    int begin = tid * CH;
    int end = begin + CH; if (end > NN) end = NN;
    if (begin > NN) begin = NN;
    int s = 0;
    for (int i = begin; i < end; i++) s += g_cnt[i];
    sh[tid] = s;
    __syncthreads();
    for (int off = 1; off < T; off <<= 1) {
        int v = (tid >= off) ? sh[tid - off] : 0;
        __syncthreads();
        sh[tid] += v;
        __syncthreads();
    }
    int run = sh[tid] - s;
    for (int i = begin; i < end; i++) {
        g_rowptr[i] = run;
        g_fill[i] = run;
        run += g_cnt[i];
    }
    if (tid == T - 1) g_rowptr[NN] = sh[T - 1];
}

// ---------------- scatter into CSR (launch 3) ----------------
__global__ void k_scatter(int E) {
    int j = blockIdx.x * blockDim.x + threadIdx.x;
    if (j >= E) return;
    int pos = atomicAdd(&g_fill[g_dst[j]], 1);
    g_srcs[pos] = g_src[j];
}

// ---------------- register-tiled GEMM + fused score projections ----------
// 128 threads per block compute a 128x64 tile of h = x @ W.
// Thread (tx = t&7, ty = t>>3) owns an 8x8 register tile:
//   rows ty*8..+8, cols tx*8..+8.
// x tile stored k-major (transposed) in smem; W stored k-major natively.
// Epilogue also computes s_src = h@a_s, s_dst = h@a_d (shfl-reduce over tx).
__global__ void __launch_bounds__(128) k_gemm(
        const float* __restrict__ xext, int use_ext,
        const float* __restrict__ W,
        const float* __restrict__ a_s,
        const float* __restrict__ a_d) {
    __shared__ float xs[DD][BR];    // 32 KB  (xs[k][row_local])
    __shared__ float ws[DD][DD];    // 16 KB  (ws[k][col])
    const float* x = use_ext ? xext : g_buf;
    int t = threadIdx.x;
    int rb = blockIdx.x * BR;

    // load W (identity copy, float4)
    {
        const float4* Wv = (const float4*)W;
        float4* wsv = (float4*)ws;
        for (int i = t; i < DD * DD / 4; i += 128) wsv[i] = Wv[i];
    }
    // load + transpose x tile: thread t owns local row t
    {
        int row = rb + t;
        int rs = (row < NN) ? row : 0;
        const float4* xr = (const float4*)(x + (size_t)rs * DD);
#pragma unroll
        for (int q = 0; q < 16; q++) {
            float4 v = xr[q];
            xs[q * 4 + 0][t] = v.x;
            xs[q * 4 + 1][t] = v.y;
            xs[q * 4 + 2][t] = v.z;
            xs[q * 4 + 3][t] = v.w;
        }
    }
    __syncthreads();

    int tx = t & 7, ty = t >> 3;
    float acc[8][8];
#pragma unroll
    for (int i = 0; i < 8; i++)
#pragma unroll
        for (int j = 0; j < 8; j++) acc[i][j] = 0.f;

    const float4* xs4 = (const float4*)xs;   // stride 32 float4 per k
    const float4* ws4 = (const float4*)ws;   // stride 16 float4 per k

#pragma unroll 8
    for (int k = 0; k < DD; k++) {
        float4 a0 = xs4[k * (BR / 4) + ty * 2];
        float4 a1 = xs4[k * (BR / 4) + ty * 2 + 1];
        float4 b0 = ws4[k * (DD / 4) + tx * 2];
        float4 b1 = ws4[k * (DD / 4) + tx * 2 + 1];
        float av[8] = {a0.x, a0.y, a0.z, a0.w, a1.x, a1.y, a1.z, a1.w};
        float bv[8] = {b0.x, b0.y, b0.z, b0.w, b1.x, b1.y, b1.z, b1.w};
#pragma unroll
        for (int i = 0; i < 8; i++)
#pragma unroll
            for (int j = 0; j < 8; j++)
                acc[i][j] = fmaf(av[i], bv[j], acc[i][j]);
    }

    // epilogue: store h, compute score projections
    float as[8], ad[8];
#pragma unroll
    for (int j = 0; j < 8; j++) {
        as[j] = a_s[tx * 8 + j];
        ad[j] = a_d[tx * 8 + j];
    }
    float4* h4 = (float4*)g_h;
#pragma unroll
    for (int i = 0; i < 8; i++) {
        int row = rb + ty * 8 + i;
        float ss = 0.f, sd = 0.f;
#pragma unroll
        for (int j = 0; j < 8; j++) {
            ss = fmaf(acc[i][j], as[j], ss);
            sd = fmaf(acc[i][j], ad[j], sd);
        }
#pragma unroll
        for (int o = 4; o; o >>= 1) {
            ss += __shfl_xor_sync(0xffffffffu, ss, o);
            sd += __shfl_xor_sync(0xffffffffu, sd, o);
        }
        if (row < NN) {
            float4 v0 = make_float4(acc[i][0], acc[i][1], acc[i][2], acc[i][3]);
            float4 v1 = make_float4(acc[i][4], acc[i][5], acc[i][6], acc[i][7]);
            h4[(size_t)row * 16 + tx * 2]     = v0;
            h4[(size_t)row * 16 + tx * 2 + 1] = v1;
            if (tx == 0) { g_ssrc[row] = ss; g_sdst[row] = sd; }
        }
    }
}

// ---------------- per-dst softmax + weighted aggregation ----------------
// One warp per destination node; pass 3 uses two 16-lane halves (float4,
// 2 edges/iter). Optional fused ELU. No atomics.
__global__ void k_agg(float* __restrict__ yext, int use_ext, int do_elu) {
    int w = (blockIdx.x * blockDim.x + threadIdx.x) >> 5;
    int lane = threadIdx.x & 31;
    if (w >= NN) return;
    float* y = use_ext ? yext : g_buf;
    int start = g_rowptr[w], end = g_rowptr[w + 1];
    float sd = g_sdst[w];

    // pass 1: segment max of leaky-relu scores
    float mx = -1e30f;
    for (int j = start + lane; j < end; j += 32) {
        float e = g_ssrc[g_srcs[j]] + sd;
        e = (e > 0.f) ? e : 0.2f * e;
        mx = fmaxf(mx, e);
    }
#pragma unroll
    for (int o = 16; o; o >>= 1) mx = fmaxf(mx, __shfl_xor_sync(0xffffffffu, mx, o));

    // pass 2: segment sum of exp
    float z = 0.f;
    for (int j = start + lane; j < end; j += 32) {
        float e = g_ssrc[g_srcs[j]] + sd;
        e = (e > 0.f) ? e : 0.2f * e;
        z += __expf(e - mx);
    }
#pragma unroll
    for (int o = 16; o; o >>= 1) z += __shfl_xor_sync(0xffffffffu, z, o);
    float inv = 1.f / (z + 1e-16f);

    // pass 3: two half-warps, 2 edges per iteration, float4 per lane
    int half = lane >> 4, l16 = lane & 15;
    float4 acc = make_float4(0.f, 0.f, 0.f, 0.f);
    const float4* h4 = (const float4*)g_h;
    for (int j = start + half; j < end; j += 2) {
        int s = g_srcs[j];
        float e = g_ssrc[s] + sd;
        e = (e > 0.f) ? e : 0.2f * e;
        float wgt = __expf(e - mx) * inv;
        float4 hv = h4[(size_t)s * 16 + l16];
        acc.x = fmaf(hv.x, wgt, acc.x);
        acc.y = fmaf(hv.y, wgt, acc.y);
        acc.z = fmaf(hv.z, wgt, acc.z);
        acc.w = fmaf(hv.w, wgt, acc.w);
    }
    acc.x += __shfl_xor_sync(0xffffffffu, acc.x, 16);
    acc.y += __shfl_xor_sync(0xffffffffu, acc.y, 16);
    acc.z += __shfl_xor_sync(0xffffffffu, acc.z, 16);
    acc.w += __shfl_xor_sync(0xffffffffu, acc.w, 16);
    if (half == 0) {
        if (do_elu) {
            acc.x = (acc.x > 0.f) ? acc.x : (__expf(acc.x) - 1.f);
            acc.y = (acc.y > 0.f) ? acc.y : (__expf(acc.y) - 1.f);
            acc.z = (acc.z > 0.f) ? acc.z : (__expf(acc.z) - 1.f);
            acc.w = (acc.w > 0.f) ? acc.w : (__expf(acc.w) - 1.f);
        }
        ((float4*)y)[(size_t)w * 16 + l16] = acc;
    }
}

// ---------------- launch ----------------
extern "C" void kernel_launch(void* const* d_in, const int* in_sizes, int n_in,
                              void* d_out, int out_size) {
    const float* feat  = (const float*)d_in[0];
    const void*  eidx  = d_in[1];
    const float* W1    = (const float*)d_in[2];
    const float* a_s1  = (const float*)d_in[3];
    const float* a_d1  = (const float*)d_in[4];
    const float* W2    = (const float*)d_in[5];
    const float* a_s2  = (const float*)d_in[6];
    const float* a_d2  = (const float*)d_in[7];
    float* out = (float*)d_out;

    int E = in_sizes[1] / 2;

    // CSR build: 4 launches (dst structure shared by all 8 convs)
    k_detect_zero<<<(NN + 1023) / 1024, 1024>>>((const int*)eidx);
    k_convert_hist<<<(E + 255) / 256, 256>>>(eidx, E);
    k_scan<<<1, 1024>>>();
    k_scatter<<<(E + 255) / 256, 256>>>(E);

    const int gemm_grid = (NN + BR - 1) / BR;
    const int agg_grid  = (NN * 32 + 255) / 256;

    for (int layer = 0; layer < 2; layer++) {
        const float* W  = layer ? W2   : W1;
        const float* as = layer ? a_s2 : a_s1;
        const float* ad = layer ? a_d2 : a_d1;
        for (int head = 0; head < 4; head++) {
            int first = (layer == 0 && head == 0);
            int last  = (layer == 1 && head == 3);
            int eol   = (head == 3);   // end-of-layer: apply ELU
            k_gemm<<<gemm_grid, 128>>>(feat, first, W + head * DD * DD,
                                       as + head * DD, ad + head * DD);
            k_agg<<<agg_grid, 256>>>(out, last, eol);
        }
    }
}

// round 4
// speedup vs baseline: 1.6945x; 1.0119x over previous
#include <cuda_runtime.h>
#include <cuda_fp16.h>
#include <math.h>
#include <stdint.h>

#define NN 50000
#define EE 800000
#define DD 64
#define BR 128   // rows per GEMM block

// ---------------- device scratch (static, no allocation) ----------------
__device__ int   g_flag;                 // 1 if edge_index is int64
__device__ int   g_cnt[NN];
__device__ int   g_rowptr[NN + 1];
__device__ int   g_fill[NN];
__device__ unsigned short g_srcs16[EE];  // src ids sorted by dst (CSR), packed
__device__ int   g_src[EE];
__device__ int   g_dst[EE];
__device__ __align__(16) float  g_buf[NN * DD];    // layer activation buffer (fp32)
__device__ __align__(16) __half g_hh[NN * DD];     // per-conv h = x @ W (fp16)
__device__ float g_ssrc[NN];
__device__ float g_sdst[NN];

// ---------------- detect dtype + zero counters (launch 0) ----------------
__global__ void k_detect_zero(const int* __restrict__ raw) {
    int i = blockIdx.x * blockDim.x + threadIdx.x;
    if (i < NN) g_cnt[i] = 0;
    if (blockIdx.x == 0) {
        __shared__ int ok;
        if (threadIdx.x == 0) ok = 1;
        __syncthreads();
        for (int j = threadIdx.x; j < 4096; j += blockDim.x)
            if (raw[2 * j + 1] != 0) ok = 0;
        __syncthreads();
        if (threadIdx.x == 0) g_flag = ok;
    }
}

// ---------------- convert + histogram, 4 edges/thread (launch 1) --------
__global__ void k_convert_hist(const void* __restrict__ raw, int E) {
    int base = (blockIdx.x * blockDim.x + threadIdx.x) * 4;
    if (g_flag) {
        const long long* p = (const long long*)raw;
#pragma unroll
        for (int u = 0; u < 4; u++) {
            int j = base + u;
            if (j < E) {
                int s = (int)p[j], d = (int)p[E + j];
                g_src[j] = s; g_dst[j] = d;
                atomicAdd(&g_cnt[d], 1);
            }
        }
    } else {
        const int* p = (const int*)raw;
#pragma unroll
        for (int u = 0; u < 4; u++) {
            int j = base + u;
            if (j < E) {
                int s = p[j], d = p[E + j];
                g_src[j] = s; g_dst[j] = d;
                atomicAdd(&g_cnt[d], 1);
            }
        }
    }
}

// ---------------- single-block scan (launch 2) ----------------
__global__ void k_scan() {
    const int T = 1024;
    const int CH = (NN + T - 1) / T;
    __shared__ int sh[T];
    int tid = threadIdx.x;
    int begin = tid * CH;
    int end = begin + CH; if (end > NN) end = NN;
    if (begin > NN) begin = NN;
    int s = 0;
    for (int i = begin; i < end; i++) s += g_cnt[i];
    sh[tid] = s;
    __syncthreads();
    for (int off = 1; off < T; off <<= 1) {
        int v = (tid >= off) ? sh[tid - off] : 0;
        __syncthreads();
        sh[tid] += v;
        __syncthreads();
    }
    int run = sh[tid] - s;
    for (int i = begin; i < end; i++) {
        g_rowptr[i] = run;
        g_fill[i] = run;
        run += g_cnt[i];
    }
    if (tid == T - 1) g_rowptr[NN] = sh[T - 1];
}

// ---------------- scatter into CSR, 4 edges/thread (launch 3) -----------
__global__ void k_scatter(int E) {
    int base = (blockIdx.x * blockDim.x + threadIdx.x) * 4;
#pragma unroll
    for (int u = 0; u < 4; u++) {
        int j = base + u;
        if (j < E) {
            int pos = atomicAdd(&g_fill[g_dst[j]], 1);
            g_srcs16[pos] = (unsigned short)g_src[j];
        }
    }
}

// ---------------- register-tiled GEMM + fused score projections ----------
// 128 threads compute a 128x64 tile of h = x @ W; thread (tx=t&7, ty=t>>3)
// owns rows ty*8..+8 x cols tx*8..+8. h written fp16; s_src/s_dst in fp32.
__global__ void __launch_bounds__(128) k_gemm(
        const float* __restrict__ xext, int use_ext,
        const float* __restrict__ W,
        const float* __restrict__ a_s,
        const float* __restrict__ a_d) {
    __shared__ float xs[DD][BR];
    __shared__ float ws[DD][DD];
    const float* x = use_ext ? xext : g_buf;
    int t = threadIdx.x;
    int rb = blockIdx.x * BR;

    {
        const float4* Wv = (const float4*)W;
        float4* wsv = (float4*)ws;
        for (int i = t; i < DD * DD / 4; i += 128) wsv[i] = Wv[i];
    }
    {
        int row = rb + t;
        int rs = (row < NN) ? row : 0;
        const float4* xr = (const float4*)(x + (size_t)rs * DD);
#pragma unroll
        for (int q = 0; q < 16; q++) {
            float4 v = xr[q];
            xs[q * 4 + 0][t] = v.x;
            xs[q * 4 + 1][t] = v.y;
            xs[q * 4 + 2][t] = v.z;
            xs[q * 4 + 3][t] = v.w;
        }
    }
    __syncthreads();

    int tx = t & 7, ty = t >> 3;
    float acc[8][8];
#pragma unroll
    for (int i = 0; i < 8; i++)
#pragma unroll
        for (int j = 0; j < 8; j++) acc[i][j] = 0.f;

    const float4* xs4 = (const float4*)xs;
    const float4* ws4 = (const float4*)ws;

#pragma unroll 8
    for (int k = 0; k < DD; k++) {
        float4 a0 = xs4[k * (BR / 4) + ty * 2];
        float4 a1 = xs4[k * (BR / 4) + ty * 2 + 1];
        float4 b0 = ws4[k * (DD / 4) + tx * 2];
        float4 b1 = ws4[k * (DD / 4) + tx * 2 + 1];
        float av[8] = {a0.x, a0.y, a0.z, a0.w, a1.x, a1.y, a1.z, a1.w};
        float bv[8] = {b0.x, b0.y, b0.z, b0.w, b1.x, b1.y, b1.z, b1.w};
#pragma unroll
        for (int i = 0; i < 8; i++)
#pragma unroll
            for (int j = 0; j < 8; j++)
                acc[i][j] = fmaf(av[i], bv[j], acc[i][j]);
    }

    float as[8], ad[8];
#pragma unroll
    for (int j = 0; j < 8; j++) {
        as[j] = a_s[tx * 8 + j];
        ad[j] = a_d[tx * 8 + j];
    }
    uint4* h16 = (uint4*)g_hh;   // row = 64 halfs = 8 uint4
#pragma unroll
    for (int i = 0; i < 8; i++) {
        int row = rb + ty * 8 + i;
        float ss = 0.f, sd = 0.f;
#pragma unroll
        for (int j = 0; j < 8; j++) {
            ss = fmaf(acc[i][j], as[j], ss);
            sd = fmaf(acc[i][j], ad[j], sd);
        }
#pragma unroll
        for (int o = 4; o; o >>= 1) {
            ss += __shfl_xor_sync(0xffffffffu, ss, o);
            sd += __shfl_xor_sync(0xffffffffu, sd, o);
        }
        if (row < NN) {
            uint4 pk;
            *reinterpret_cast<__half2*>(&pk.x) = __floats2half2_rn(acc[i][0], acc[i][1]);
            *reinterpret_cast<__half2*>(&pk.y) = __floats2half2_rn(acc[i][2], acc[i][3]);
            *reinterpret_cast<__half2*>(&pk.z) = __floats2half2_rn(acc[i][4], acc[i][5]);
            *reinterpret_cast<__half2*>(&pk.w) = __floats2half2_rn(acc[i][6], acc[i][7]);
            h16[(size_t)row * 8 + tx] = pk;
            if (tx == 0) { g_ssrc[row] = ss; g_sdst[row] = sd; }
        }
    }
}

// ---------------- per-dst softmax (online) + weighted aggregation --------
// One warp per dst node. Pass A: online max+sum in one sweep.
// Pass B: two 16-lane halves, 2 edges/iter, 8B (4 fp16) per lane per edge.
__global__ void k_agg(float* __restrict__ yext, int use_ext, int do_elu) {
    int w = (blockIdx.x * blockDim.x + threadIdx.x) >> 5;
    int lane = threadIdx.x & 31;
    if (w >= NN) return;
    float* y = use_ext ? yext : g_buf;
    int start = g_rowptr[w], end = g_rowptr[w + 1];
    float sd = g_sdst[w];

    // pass A: per-lane online softmax stats, then warp combine
    float m = -1e30f, z = 0.f;
    for (int j = start + lane; j < end; j += 32) {
        float e = g_ssrc[g_srcs16[j]] + sd;
        e = (e > 0.f) ? e : 0.2f * e;
        if (e > m) { z *= __expf(m - e); m = e; }
        z += __expf(e - m);
    }
    float M = m;
#pragma unroll
    for (int o = 16; o; o >>= 1) M = fmaxf(M, __shfl_xor_sync(0xffffffffu, M, o));
    z *= __expf(m - M);
#pragma unroll
    for (int o = 16; o; o >>= 1) z += __shfl_xor_sync(0xffffffffu, z, o);
    float inv = 1.f / (z + 1e-16f);

    // pass B
    int half = lane >> 4, l16 = lane & 15;
    float4 acc = make_float4(0.f, 0.f, 0.f, 0.f);
    const uint2* h8 = (const uint2*)g_hh;   // row = 16 uint2 (4 halfs each)
    for (int j = start + half; j < end; j += 2) {
        int s = g_srcs16[j];
        float e = g_ssrc[s] + sd;
        e = (e > 0.f) ? e : 0.2f * e;
        float wgt = __expf(e - M) * inv;
        uint2 hv = h8[(size_t)s * 16 + l16];
        float2 f0 = __half22float2(*reinterpret_cast<const __half2*>(&hv.x));
        float2 f1 = __half22float2(*reinterpret_cast<const __half2*>(&hv.y));
        acc.x = fmaf(f0.x, wgt, acc.x);
        acc.y = fmaf(f0.y, wgt, acc.y);
        acc.z = fmaf(f1.x, wgt, acc.z);
        acc.w = fmaf(f1.y, wgt, acc.w);
    }
    acc.x += __shfl_xor_sync(0xffffffffu, acc.x, 16);
    acc.y += __shfl_xor_sync(0xffffffffu, acc.y, 16);
    acc.z += __shfl_xor_sync(0xffffffffu, acc.z, 16);
    acc.w += __shfl_xor_sync(0xffffffffu, acc.w, 16);
    if (half == 0) {
        if (do_elu) {
            acc.x = (acc.x > 0.f) ? acc.x : (__expf(acc.x) - 1.f);
            acc.y = (acc.y > 0.f) ? acc.y : (__expf(acc.y) - 1.f);
            acc.z = (acc.z > 0.f) ? acc.z : (__expf(acc.z) - 1.f);
            acc.w = (acc.w > 0.f) ? acc.w : (__expf(acc.w) - 1.f);
        }
        ((float4*)y)[(size_t)w * 16 + l16] = acc;
    }
}

// ---------------- launch ----------------
extern "C" void kernel_launch(void* const* d_in, const int* in_sizes, int n_in,
                              void* d_out, int out_size) {
    const float* feat  = (const float*)d_in[0];
    const void*  eidx  = d_in[1];
    const float* W1    = (const float*)d_in[2];
    const float* a_s1  = (const float*)d_in[3];
    const float* a_d1  = (const float*)d_in[4];
    const float* W2    = (const float*)d_in[5];
    const float* a_s2  = (const float*)d_in[6];
    const float* a_d2  = (const float*)d_in[7];
    float* out = (float*)d_out;

    int E = in_sizes[1] / 2;

    k_detect_zero<<<(NN + 1023) / 1024, 1024>>>((const int*)eidx);
    k_convert_hist<<<(E / 4 + 255) / 256, 256>>>(eidx, E);
    k_scan<<<1, 1024>>>();
    k_scatter<<<(E / 4 + 255) / 256, 256>>>(E);

    const int gemm_grid = (NN + BR - 1) / BR;
    const int agg_grid  = (NN * 32 + 255) / 256;

    for (int layer = 0; layer < 2; layer++) {
        const float* W  = layer ? W2   : W1;
        const float* as = layer ? a_s2 : a_s1;
        const float* ad = layer ? a_d2 : a_d1;
        for (int head = 0; head < 4; head++) {
            int first = (layer == 0 && head == 0);
            int last  = (layer == 1 && head == 3);
            int eol   = (head == 3);
            k_gemm<<<gemm_grid, 128>>>(feat, first, W + head * DD * DD,
                                       as + head * DD, ad + head * DD);
            k_agg<<<agg_grid, 256>>>(out, last, eol);
        }
    }
}